// round 16
// baseline (speedup 1.0000x reference)
#include <cuda_runtime.h>
#include <cuda_fp16.h>
#include <math.h>
#include <stdint.h>

#define T_LEN   8192
#define BATCH   4
#define IN_DIM  512
#define D_V     512
#define D_K     64
#define CHUNK   128
#define NC      (T_LEN / CHUNK)          // 64
#define NPROJ   (D_V + 3 * D_K)          // 704 = 11 * 64
#define MROWS   (T_LEN * BATCH)          // 32768
#define EPS_F   1e-8f
#define SEG     (BATCH * D_K * D_V)      // 131072 state elements
#define AQW     192                      // A(128) | qt(64) fused row width

// ---------------- static device scratch ----------------
__device__ __align__(128) float g_bias[NPROJ];
__device__ __align__(128) __half g_Wh[NPROJ * IN_DIM];
__device__ __align__(128) __half g_Wl[NPROJ * IN_DIM];
__device__ __align__(128) __half g_Xh[(size_t)MROWS * IN_DIM];
__device__ __align__(128) __half g_Xl[(size_t)MROWS * IN_DIM];
__device__ __align__(128) float g_proj[(size_t)MROWS * NPROJ];             // only cols 512.. written/read
__device__ __align__(128) __half g_Vh[(size_t)MROWS * D_V];                // v fp16 [r][512]
__device__ __align__(128) __half g_AQh[(size_t)NC * BATCH * CHUNK * AQW];  // [c][b][t][A|qt]
__device__ __align__(128) __half g_kpeh[(size_t)NC * BATCH * CHUNK * D_K];
__device__ __align__(128) float g_pend[NC * BATCH * D_K];
__device__ __align__(128) __half g_Wch[(size_t)NC * SEG];                  // state writes fp16
__device__ __align__(128) __half g_Sh[(size_t)NC * SEG];                   // S_start [c][b][n][d]

// ---------------- helpers ----------------
__device__ __forceinline__ uint32_t smem_u32(const void* p) {
    uint32_t a;
    asm("{ .reg .u64 t; cvta.to.shared.u64 t, %1; cvt.u32.u64 %0, t; }" : "=r"(a) : "l"(p));
    return a;
}
__device__ __forceinline__ void cp16(uint32_t dst, const void* src) {
    asm volatile("cp.async.cg.shared.global [%0], [%1], 16;" :: "r"(dst), "l"(src));
}
#define CP_COMMIT() asm volatile("cp.async.commit_group;")
#define CP_WAIT(n)  asm volatile("cp.async.wait_group %0;" :: "n"(n))

__device__ __forceinline__ void mma_f16(float* c, const uint32_t* a, const uint32_t* b) {
    asm volatile(
        "mma.sync.aligned.m16n8k16.row.col.f32.f16.f16.f32 "
        "{%0,%1,%2,%3}, {%4,%5,%6,%7}, {%8,%9}, {%0,%1,%2,%3};"
        : "+f"(c[0]), "+f"(c[1]), "+f"(c[2]), "+f"(c[3])
        : "r"(a[0]), "r"(a[1]), "r"(a[2]), "r"(a[3]), "r"(b[0]), "r"(b[1]));
}
__device__ __forceinline__ void ldm_x4(uint32_t& r0, uint32_t& r1, uint32_t& r2, uint32_t& r3,
                                       uint32_t addr) {
    asm volatile("ldmatrix.sync.aligned.m8n8.x4.shared.b16 {%0,%1,%2,%3}, [%4];"
                 : "=r"(r0), "=r"(r1), "=r"(r2), "=r"(r3) : "r"(addr));
}
__device__ __forceinline__ void ldm_x4_trans(uint32_t& r0, uint32_t& r1, uint32_t& r2, uint32_t& r3,
                                             uint32_t addr) {
    asm volatile("ldmatrix.sync.aligned.m8n8.x4.trans.shared.b16 {%0,%1,%2,%3}, [%4];"
                 : "=r"(r0), "=r"(r1), "=r"(r2), "=r"(r3) : "r"(addr));
}
__device__ __forceinline__ uint32_t pack2h(__half a, __half b) {
    return ((uint32_t)*(uint16_t*)&b << 16) | *(uint16_t*)&a;
}
__device__ __forceinline__ void split_f16(float v, __half& h, __half& l) {
    h = __float2half_rn(v);
    l = __float2half_rn(v - __half2float(h));
}

// ---------------- kernel 0: fused convx + pack ----------------
#define CONV_BLOCKS ((int)(((size_t)MROWS * IN_DIM / 8) / 256))   // 8192
#define PACK_BLOCKS ((NPROJ * IN_DIM + 255) / 256)                // 1408

__global__ void __launch_bounds__(256) convpack_kernel(
    const float* __restrict__ X,
    const float* __restrict__ Wv, const float* __restrict__ bv,
    const float* __restrict__ Wk, const float* __restrict__ bk,
    const float* __restrict__ Wq, const float* __restrict__ bq,
    const float* __restrict__ Wa, const float* __restrict__ ba) {
    if (blockIdx.x < CONV_BLOCKS) {
        size_t e0 = ((size_t)blockIdx.x * 256 + threadIdx.x) * 8;
        float4 v0 = *(const float4*)&X[e0];
        float4 v1 = *(const float4*)&X[e0 + 4];
        float f[8] = {v0.x, v0.y, v0.z, v0.w, v1.x, v1.y, v1.z, v1.w};
        __align__(16) __half hh[8], ll[8];
#pragma unroll
        for (int i = 0; i < 8; i++) split_f16(f[i], hh[i], ll[i]);
        *(uint4*)&g_Xh[e0] = *(uint4*)hh;
        *(uint4*)&g_Xl[e0] = *(uint4*)ll;
    } else {
        int idx = (blockIdx.x - CONV_BLOCKS) * 256 + threadIdx.x;
        if (idx < NPROJ * IN_DIM) {
            int o = idx >> 9, i = idx & 511;
            float v;
            if (o < 512)       v = Wv[o * IN_DIM + i];
            else if (o < 576)  v = Wk[(o - 512) * IN_DIM + i];
            else if (o < 640)  v = Wq[(o - 576) * IN_DIM + i];
            else               v = Wa[(o - 640) * IN_DIM + i];
            __half h, l; split_f16(v, h, l);
            g_Wh[idx] = h;
            g_Wl[idx] = l;
        }
        if (idx < NPROJ) {
            float v;
            if (idx < 512)      v = bv[idx];
            else if (idx < 576) v = bk[idx - 512];
            else if (idx < 640) v = bq[idx - 576];
            else                v = ba[idx - 640];
            g_bias[idx] = v;
        }
    }
}

// ---------------- kernel 2: projection GEMM, M=128 N=64 tile ----------------------
// v/k/q tiles (bx<10): 1-term fp16. alpha (bx=10): 3-term.
#define GP 72
#define GSTAGE ((2 * 128 + 2 * 64) * GP)
#define GM_SMEM (2 * GSTAGE * 2)

__global__ void __launch_bounds__(256, 2) gemm_mma_kernel() {
    extern __shared__ __half sm_b[];
    uint32_t sb = smem_u32(sm_b);

    int tid = threadIdx.x, wid = tid >> 5, lane = tid & 31;
    int g = lane >> 2, tig = lane & 3;
    int lq = lane & 7, lseg = lane >> 3;
    int wm = wid >> 1;
    int wn = wid & 1;
    int bx = blockIdx.x;
    int m0 = blockIdx.y * 128;
    int n0 = bx * 64;
    bool full = (bx == 10);          // alpha tile: 3-term

    float acc[2][4][4];
#pragma unroll
    for (int i = 0; i < 2; i++)
#pragma unroll
        for (int j = 0; j < 4; j++)
#pragma unroll
            for (int k = 0; k < 4; k++) acc[i][j][k] = 0.f;

#define GCOPY(ch, buf) do {                                                              \
    uint32_t base = sb + (uint32_t)(buf) * (GSTAGE * 2);                                 \
    _Pragma("unroll")                                                                    \
    for (int u = 0; u < 4; u++) {                                                        \
        int l = tid + u * 256;                                                           \
        int rr = l >> 3, qq = l & 7;                                                     \
        size_t gx = (size_t)(m0 + rr) * IN_DIM + (ch) * 64 + qq * 8;                     \
        uint32_t so = (uint32_t)(rr * GP + qq * 8) * 2;                                  \
        cp16(base + so, &g_Xh[gx]);                                                      \
        if (full) cp16(base + 128 * GP * 2 + so, &g_Xl[gx]);                             \
    }                                                                                    \
    _Pragma("unroll")                                                                    \
    for (int u = 0; u < 2; u++) {                                                        \
        int l = tid + u * 256;                                                           \
        int rr = l >> 3, qq = l & 7;                                                     \
        size_t gw = (size_t)(n0 + rr) * IN_DIM + (ch) * 64 + qq * 8;                     \
        uint32_t so = (uint32_t)(rr * GP + qq * 8) * 2;                                  \
        cp16(base + 2 * 128 * GP * 2 + so, &g_Wh[gw]);                                   \
        if (full) cp16(base + (2 * 128 + 64) * GP * 2 + so, &g_Wl[gw]);                  \
    }                                                                                    \
} while (0)

    GCOPY(0, 0);
    CP_COMMIT();

    int arow = (lseg & 1) * 8 + lq;
    int asel = (lseg >> 1) * 8;
    int brow = (lseg >> 1) * 8 + lq;
    int bsel = (lseg & 1) * 8;

    for (int ch = 0; ch < 8; ch++) {
        if (ch + 1 < 8) { GCOPY(ch + 1, (ch + 1) & 1); CP_COMMIT(); }
        if (ch + 1 < 8) CP_WAIT(1); else CP_WAIT(0);
        __syncthreads();

        uint32_t uXh = sb + (uint32_t)(ch & 1) * (GSTAGE * 2);
        uint32_t uXl = uXh + 128 * GP * 2;
        uint32_t uWh = uXl + 128 * GP * 2;
        uint32_t uWl = uWh + 64 * GP * 2;

#pragma unroll
        for (int ks = 0; ks < 64; ks += 16) {
            uint32_t Ah[2][4], Al[2][4], Bh[4][2], Bl[4][2];
#pragma unroll
            for (int mi = 0; mi < 2; mi++) {
                uint32_t off = (uint32_t)((wm * 32 + mi * 16 + arow) * GP + ks + asel) * 2;
                ldm_x4(Ah[mi][0], Ah[mi][1], Ah[mi][2], Ah[mi][3], uXh + off);
                if (full) ldm_x4(Al[mi][0], Al[mi][1], Al[mi][2], Al[mi][3], uXl + off);
            }
#pragma unroll
            for (int njp = 0; njp < 2; njp++) {
                uint32_t off = (uint32_t)((wn * 32 + njp * 16 + brow) * GP + ks + bsel) * 2;
                ldm_x4(Bh[njp * 2][0], Bh[njp * 2][1], Bh[njp * 2 + 1][0], Bh[njp * 2 + 1][1], uWh + off);
                if (full) ldm_x4(Bl[njp * 2][0], Bl[njp * 2][1], Bl[njp * 2 + 1][0], Bl[njp * 2 + 1][1], uWl + off);
            }
#pragma unroll
            for (int mi = 0; mi < 2; mi++)
#pragma unroll
                for (int nj = 0; nj < 4; nj++) {
                    mma_f16(acc[mi][nj], Ah[mi], Bh[nj]);
                    if (full) {
                        mma_f16(acc[mi][nj], Ah[mi], Bl[nj]);
                        mma_f16(acc[mi][nj], Al[mi], Bh[nj]);
                    }
                }
        }
        __syncthreads();
    }

    bool alpha_tile = (bx == 10);
    bool v_tile = (bx < 8);
#pragma unroll
    for (int mi = 0; mi < 2; mi++) {
        int r0 = m0 + wm * 32 + mi * 16 + g;
#pragma unroll
        for (int nj = 0; nj < 4; nj++) {
            int col = n0 + wn * 32 + nj * 8 + tig * 2;
            float b0 = g_bias[col], b1 = g_bias[col + 1];
            float v0 = acc[mi][nj][0] + b0, v1 = acc[mi][nj][1] + b1;
            float v2 = acc[mi][nj][2] + b0, v3 = acc[mi][nj][3] + b1;
            if (v_tile) {
                *(uint32_t*)&g_Vh[(size_t)r0 * D_V + col] =
                    pack2h(__float2half_rn(v0), __float2half_rn(v1));
                *(uint32_t*)&g_Vh[(size_t)(r0 + 8) * D_V + col] =
                    pack2h(__float2half_rn(v2), __float2half_rn(v3));
            } else {
                if (alpha_tile) {
                    v0 = 1.f / (1.f + expf(-v0));
                    v1 = 1.f / (1.f + expf(-v1));
                    v2 = 1.f / (1.f + expf(-v2));
                    v3 = 1.f / (1.f + expf(-v3));
                }
                float2 lo; lo.x = v0; lo.y = v1;
                float2 hi; hi.x = v2; hi.y = v3;
                *(float2*)&g_proj[(size_t)r0 * NPROJ + col] = lo;
                *(float2*)&g_proj[(size_t)(r0 + 8) * NPROJ + col] = hi;
            }
        }
    }
#undef GCOPY
}

// ---------------- kernel 3: per-chunk prep -> p, kpe(fp16), AQ(fp16) -------------
#define PREP_SMEM (3 * 128 * 65 * 4)
__global__ void __launch_bounds__(256) prep_kernel() {
    extern __shared__ float sm[];
    float* sp  = sm;
    float* sqt = sm + 128 * 65;
    float* skt = sm + 2 * 128 * 65;

    int b = blockIdx.x, c = blockIdx.y;
    int tid = threadIdx.x;
    size_t aqbase = (size_t)(c * BATCH + b) * CHUNK * AQW;
    size_t kbase  = (size_t)(c * BATCH + b) * CHUNK * D_K;

#pragma unroll
    for (int j = 0; j < 8; j++) {
        int l  = tid + j * 256;
        int t  = l >> 4;
        int c4 = (l & 15) * 4;
        const float* rowp = g_proj + (size_t)((c * CHUNK + t) * BATCH + b) * NPROJ;
        float4 av = *(const float4*)&rowp[640 + c4];
        skt[t * 65 + c4 + 0] = av.x; skt[t * 65 + c4 + 1] = av.y;
        skt[t * 65 + c4 + 2] = av.z; skt[t * 65 + c4 + 3] = av.w;
    }
    __syncthreads();

    if (tid < D_K) {
        float p = 1.f;
        for (int t = 0; t < CHUNK; t++) {
            p *= fmaxf(skt[t * 65 + tid], EPS_F);
            sp[t * 65 + tid] = p;
        }
        g_pend[(c * BATCH + b) * D_K + tid] = p;
    }
    __syncthreads();

#pragma unroll
    for (int j = 0; j < 8; j++) {
        int l  = tid + j * 256;
        int t  = l >> 4;
        int c4 = (l & 15) * 4;
        const float* rowp = g_proj + (size_t)((c * CHUNK + t) * BATCH + b) * NPROJ;
        float4 qv = *(const float4*)&rowp[576 + c4];
        float4 kv = *(const float4*)&rowp[512 + c4];
        float p0 = sp[t * 65 + c4 + 0], p1 = sp[t * 65 + c4 + 1];
        float p2 = sp[t * 65 + c4 + 2], p3 = sp[t * 65 + c4 + 3];
        float pe0 = sp[127 * 65 + c4 + 0], pe1 = sp[127 * 65 + c4 + 1];
        float pe2 = sp[127 * 65 + c4 + 2], pe3 = sp[127 * 65 + c4 + 3];
        float q0 = qv.x * p0, q1 = qv.y * p1, q2 = qv.z * p2, q3 = qv.w * p3;
        float k0 = kv.x / (p0 + EPS_F), k1 = kv.y / (p1 + EPS_F);
        float k2 = kv.z / (p2 + EPS_F), k3 = kv.w / (p3 + EPS_F);
        sqt[t * 65 + c4 + 0] = q0; sqt[t * 65 + c4 + 1] = q1;
        sqt[t * 65 + c4 + 2] = q2; sqt[t * 65 + c4 + 3] = q3;
        skt[t * 65 + c4 + 0] = k0; skt[t * 65 + c4 + 1] = k1;
        skt[t * 65 + c4 + 2] = k2; skt[t * 65 + c4 + 3] = k3;
        __half h0 = __float2half_rn(q0), h1 = __float2half_rn(q1);
        __half h2 = __float2half_rn(q2), h3 = __float2half_rn(q3);
        uint32_t* ph = (uint32_t*)&g_AQh[aqbase + t * AQW + 128 + c4];
        ph[0] = pack2h(h0, h1); ph[1] = pack2h(h2, h3);
        __half e0 = __float2half_rn(k0 * pe0), e1 = __float2half_rn(k1 * pe1);
        __half e2 = __float2half_rn(k2 * pe2), e3 = __float2half_rn(k3 * pe3);
        uint32_t* kh = (uint32_t*)&g_kpeh[kbase + t * D_K + c4];
        kh[0] = pack2h(e0, e1); kh[1] = pack2h(e2, e3);
    }
    __syncthreads();

    int sxl = tid & 15;
    int t0  = (tid >> 4) * 8;
    float acc[8][8];
#pragma unroll
    for (int i = 0; i < 8; i++)
#pragma unroll
        for (int j = 0; j < 8; j++) acc[i][j] = 0.f;

    for (int n = 0; n < D_K; n++) {
        float qv[8], kv[8];
#pragma unroll
        for (int i = 0; i < 8; i++) qv[i] = sqt[(t0 + i) * 65 + n];
#pragma unroll
        for (int j = 0; j < 8; j++) kv[j] = skt[(sxl + 16 * j) * 65 + n];
#pragma unroll
        for (int i = 0; i < 8; i++)
#pragma unroll
            for (int j = 0; j < 8; j++)
                acc[i][j] = fmaf(qv[i], kv[j], acc[i][j]);
    }
#pragma unroll
    for (int i = 0; i < 8; i++) {
        int t = t0 + i;
#pragma unroll
        for (int j = 0; j < 8; j++) {
            int s = sxl + 16 * j;
            float val = (t >= s) ? acc[i][j] : 0.f;
            g_AQh[aqbase + t * AQW + s] = __float2half_rn(val);
        }
    }
}

// ---------------- kernel 4: contrib via HMMA 1-term; fp16 output -----------------
#define CPP 72
#define CM_SMEM (2 * 128 * CPP * 2)

__global__ void __launch_bounds__(256) contrib_kernel() {
    extern __shared__ __half csm[];
    uint32_t uKh = smem_u32(csm);
    uint32_t uVh = uKh + 128 * CPP * 2;

    int d0 = blockIdx.x * 64, c = blockIdx.y, b = blockIdx.z;
    int tid = threadIdx.x, wid = tid >> 5, lane = tid & 31;
    int g = lane >> 2, tig = lane & 3;
    int lq = lane & 7, lseg = lane >> 3;
    int wn = wid & 1;
    int wd = wid >> 1;

    size_t kbase = (size_t)(c * BATCH + b) * CHUNK * D_K;

#pragma unroll
    for (int u = 0; u < 2; u++) {
        int l = tid + u * 256;
        int rr = l >> 3, qq = l & 7;
        uint32_t so = (uint32_t)(rr * CPP + qq * 8) * 2;
        cp16(uKh + so, &g_kpeh[kbase + rr * D_K + qq * 8]);
        size_t vs = (size_t)((c * CHUNK + rr) * BATCH + b) * D_V + d0 + qq * 8;
        cp16(uVh + so, &g_Vh[vs]);
    }
    CP_COMMIT();
#pragma unroll
    for (int u = 2; u < 4; u++) {
        int l = tid + u * 256;
        int rr = l >> 3, qq = l & 7;
        uint32_t so = (uint32_t)(rr * CPP + qq * 8) * 2;
        cp16(uKh + so, &g_kpeh[kbase + rr * D_K + qq * 8]);
        size_t vs = (size_t)((c * CHUNK + rr) * BATCH + b) * D_V + d0 + qq * 8;
        cp16(uVh + so, &g_Vh[vs]);
    }
    CP_COMMIT();

    float acc[2][2][4];
#pragma unroll
    for (int i = 0; i < 2; i++)
#pragma unroll
        for (int j = 0; j < 2; j++)
#pragma unroll
            for (int k = 0; k < 4; k++) acc[i][j][k] = 0.f;

#pragma unroll
    for (int half = 0; half < 2; half++) {
        if (half == 0) CP_WAIT(1); else CP_WAIT(0);
        __syncthreads();
#pragma unroll
        for (int kk = 0; kk < 64; kk += 16) {
            int ks = half * 64 + kk;
            uint32_t Ah[2][4], Bh[2][2];
            uint32_t arow = ks + (lseg >> 1) * 8 + lq;
#pragma unroll
            for (int mi = 0; mi < 2; mi++) {
                uint32_t col = wn * 32 + mi * 16 + (lseg & 1) * 8;
                uint32_t off = (arow * CPP + col) * 2;
                ldm_x4_trans(Ah[mi][0], Ah[mi][1], Ah[mi][2], Ah[mi][3], uKh + off);
            }
            {
                uint32_t brow = ks + (lseg & 1) * 8 + lq;
                uint32_t col = wd * 16 + (lseg >> 1) * 8;
                uint32_t off = (brow * CPP + col) * 2;
                ldm_x4_trans(Bh[0][0], Bh[0][1], Bh[1][0], Bh[1][1], uVh + off);
            }
#pragma unroll
            for (int mi = 0; mi < 2; mi++)
#pragma unroll
                for (int nj = 0; nj < 2; nj++)
                    mma_f16(acc[mi][nj], Ah[mi], Bh[nj]);
        }
    }

    __half* Wb = g_Wch + (size_t)(c * BATCH + b) * D_K * D_V;
#pragma unroll
    for (int mi = 0; mi < 2; mi++) {
        int n = wn * 32 + mi * 16 + g;
#pragma unroll
        for (int nj = 0; nj < 2; nj++) {
            int d = d0 + wd * 16 + nj * 8 + tig * 2;
            *(uint32_t*)&Wb[(size_t)n * D_V + d] =
                pack2h(__float2half_rn(acc[mi][nj][0]), __float2half_rn(acc[mi][nj][1]));
            *(uint32_t*)&Wb[(size_t)(n + 8) * D_V + d] =
                pack2h(__float2half_rn(acc[mi][nj][2]), __float2half_rn(acc[mi][nj][3]));
        }
    }
}

// ---------------- kernel 5: elementwise state scan; emit S_start fp16 -------------
__global__ void __launch_bounds__(256) state_scan_kernel() {
    int g = blockIdx.x * 256 + threadIdx.x;
    int bn = g >> 9;
    float s = 0.f;
    for (int c = 0; c < NC; c++) {
        size_t idx = (size_t)c * SEG + g;
        g_Sh[idx] = __float2half_rn(s);
        s = fmaf(s, g_pend[c * (BATCH * D_K) + bn], __half2float(g_Wch[idx]));
    }
}

// ---------------- kernel 6: Y = [A|q_t] @ [V;S], d-tile 128, causal-zero skip -----
#define YPA 72
#define YPB 136
#define YSTAGE (128 * YPA + 64 * YPB)
#define YG_SMEM (2 * YSTAGE * 2)

__global__ void __launch_bounds__(128, 2) ygemm_mma_kernel(float* __restrict__ out) {
    extern __shared__ __half ysm[];
    uint32_t sb = smem_u32(ysm);

    int d0 = blockIdx.x * 128;
    int c = blockIdx.y, b = blockIdx.z;
    int tid = threadIdx.x, w = tid >> 5, lane = tid & 31;
    int g = lane >> 2, tig = lane & 3;
    int lq = lane & 7, lseg = lane >> 3;
    int arow = (lseg & 1) * 8 + lq;
    int asel = (lseg >> 1) * 8;

    size_t aqbase = (size_t)(c * BATCH + b) * CHUNK * AQW;
    size_t sbase  = (size_t)(c * BATCH + b) * D_K * D_V;

    float acc[2][16][4];
#pragma unroll
    for (int i = 0; i < 2; i++)
#pragma unroll
        for (int j = 0; j < 16; j++)
#pragma unroll
            for (int k = 0; k < 4; k++) acc[i][j][k] = 0.f;

#define YCOPY(ch, buf) do {                                                              \
    uint32_t base = sb + (uint32_t)(buf) * (YSTAGE * 2);                                 \
    _Pragma("unroll")                                                                    \
    for (int u = 0; u < 8; u++) {                                                        \
        int l = tid + u * 128;                                                           \
        int rr = l >> 3, qq = l & 7;                                                     \
        size_t src = aqbase + rr * AQW + (ch) * 64 + qq * 8;                             \
        uint32_t so = (uint32_t)(rr * YPA + qq * 8) * 2;                                 \
        cp16(base + so, &g_AQh[src]);                                                    \
    }                                                                                    \
    _Pragma("unroll")                                                                    \
    for (int u = 0; u < 8; u++) {                                                        \
        int l = tid + u * 128;                                                           \
        int rr = l >> 4, qq = l & 15;                                                    \
        uint32_t so = (uint32_t)(128 * YPA + rr * YPB + qq * 8) * 2;                     \
        if ((ch) < 2) {                                                                  \
            size_t src = (size_t)((c * CHUNK + (ch) * 64 + rr) * BATCH + b) * D_V + d0 + qq * 8; \
            cp16(base + so, &g_Vh[src]);                                                 \
        } else {                                                                         \
            size_t src = sbase + (size_t)rr * D_V + d0 + qq * 8;                         \
            cp16(base + so, &g_Sh[src]);                                                 \
        }                                                                                \
    }                                                                                    \
} while (0)

    YCOPY(0, 0);
    CP_COMMIT();

    for (int ch = 0; ch < 3; ch++) {
        if (ch + 1 < 3) { YCOPY(ch + 1, (ch + 1) & 1); CP_COMMIT(); }
        if (ch + 1 < 3) CP_WAIT(1); else CP_WAIT(0);
        __syncthreads();

        bool active = !(ch == 1 && w < 2) && !(ch == 2 && c == 0);
        if (active) {
            uint32_t uA = sb + (uint32_t)(ch & 1) * (YSTAGE * 2);
            uint32_t uB = uA + 128 * YPA * 2;

#pragma unroll
            for (int ks = 0; ks < 64; ks += 16) {
                uint32_t Ah[2][4], Bh[16][2];
#pragma unroll
                for (int mi = 0; mi < 2; mi++) {
                    uint32_t off = (uint32_t)((w * 32 + mi * 16 + arow) * YPA + ks + asel) * 2;
                    ldm_x4(Ah[mi][0], Ah[mi][1], Ah[mi][2], Ah[mi][3], uA + off);
                }
                uint32_t row = ks + (lseg & 1) * 8 + lq;
#pragma unroll
                for (int nbs = 0; nbs < 8; nbs++) {
                    uint32_t col = nbs * 16 + (lseg >> 1) * 8;
                    uint32_t off = (row * YPB + col) * 2;
                    ldm_x4_trans(Bh[nbs * 2][0], Bh[nbs * 2][1], Bh[nbs * 2 + 1][0], Bh[nbs * 2 + 1][1], uB + off);
                }
#pragma unroll
                for (int mi = 0; mi < 2; mi++)
#pragma unroll
                    for (int nj = 0; nj < 16; nj++)
                        mma_f16(acc[mi][nj], Ah[mi], Bh[nj]);
            }
        }
        __syncthreads();
    }
#undef YCOPY

#pragma unroll
    for (int mi = 0; mi < 2; mi++) {
        int t = w * 32 + mi * 16 + g;
#pragma unroll
        for (int nj = 0; nj < 16; nj++) {
            int col = d0 + nj * 8 + tig * 2;
            float2 lo; lo.x = acc[mi][nj][0]; lo.y = acc[mi][nj][1];
            float2 hi; hi.x = acc[mi][nj][2]; hi.y = acc[mi][nj][3];
            *(float2*)&out[(size_t)((c * CHUNK + t) * BATCH + b) * D_V + col] = lo;
            *(float2*)&out[(size_t)((c * CHUNK + t + 8) * BATCH + b) * D_V + col] = hi;
        }
    }
}

// ---------------- launch ----------------
extern "C" void kernel_launch(void* const* d_in, const int* in_sizes, int n_in,
                              void* d_out, int out_size) {
    const float* x  = (const float*)d_in[0];
    const float* Wv = (const float*)d_in[1];
    const float* bv = (const float*)d_in[2];
    const float* Wk = (const float*)d_in[3];
    const float* bk = (const float*)d_in[4];
    const float* Wq = (const float*)d_in[5];
    const float* bq = (const float*)d_in[6];
    const float* Wa = (const float*)d_in[7];
    const float* ba = (const float*)d_in[8];
    float* out = (float*)d_out;

    cudaFuncSetAttribute(prep_kernel, cudaFuncAttributeMaxDynamicSharedMemorySize, PREP_SMEM);
    cudaFuncSetAttribute(gemm_mma_kernel, cudaFuncAttributeMaxDynamicSharedMemorySize, GM_SMEM);
    cudaFuncSetAttribute(contrib_kernel, cudaFuncAttributeMaxDynamicSharedMemorySize, CM_SMEM);
    cudaFuncSetAttribute(ygemm_mma_kernel, cudaFuncAttributeMaxDynamicSharedMemorySize, YG_SMEM);

    convpack_kernel<<<CONV_BLOCKS + PACK_BLOCKS, 256>>>(x, Wv, bv, Wk, bk, Wq, bq, Wa, ba);
    gemm_mma_kernel<<<dim3(11, MROWS / 128), 256, GM_SMEM>>>();
    prep_kernel<<<dim3(BATCH, NC), 256, PREP_SMEM>>>();
    contrib_kernel<<<dim3(D_V / 64, NC, BATCH), 256, CM_SMEM>>>();
    state_scan_kernel<<<SEG / 256, 256>>>();
    ygemm_mma_kernel<<<dim3(D_V / 128, NC, BATCH), 128, YG_SMEM>>>(out);
}

// round 17
// speedup vs baseline: 1.0679x; 1.0679x over previous
#include <cuda_runtime.h>
#include <cuda_fp16.h>
#include <math.h>
#include <stdint.h>

#define T_LEN   8192
#define BATCH   4
#define IN_DIM  512
#define D_V     512
#define D_K     64
#define CHUNK   128
#define NC      (T_LEN / CHUNK)          // 64
#define NPROJ   (D_V + 3 * D_K)          // 704 = 11 * 64
#define MROWS   (T_LEN * BATCH)          // 32768
#define EPS_F   1e-8f
#define SEG     (BATCH * D_K * D_V)      // 131072 state elements
#define AQW     192                      // A(128) | qt(64) fused row width

// ---------------- static device scratch ----------------
__device__ __align__(128) float g_bias[NPROJ];
__device__ __align__(128) __half g_Wh[NPROJ * IN_DIM];
__device__ __align__(128) __half g_Wl[NPROJ * IN_DIM];
__device__ __align__(128) __half g_Xh[(size_t)MROWS * IN_DIM];
__device__ __align__(128) __half g_Xl[(size_t)MROWS * IN_DIM];
__device__ __align__(128) float g_proj[(size_t)MROWS * NPROJ];             // only cols 512.. written/read
__device__ __align__(128) __half g_Vh[(size_t)MROWS * D_V];                // v fp16 [r][512]
__device__ __align__(128) __half g_AQh[(size_t)NC * BATCH * CHUNK * AQW];  // [c][b][t][A|qt]
__device__ __align__(128) __half g_kpeh[(size_t)NC * BATCH * CHUNK * D_K];
__device__ __align__(128) float g_pend[NC * BATCH * D_K];
__device__ __align__(128) float g_Wc[(size_t)NC * SEG];
__device__ __align__(128) __half g_Sh[(size_t)NC * SEG];                   // S_start [c][b][n][d]

// ---------------- helpers ----------------
__device__ __forceinline__ uint32_t smem_u32(const void* p) {
    uint32_t a;
    asm("{ .reg .u64 t; cvta.to.shared.u64 t, %1; cvt.u32.u64 %0, t; }" : "=r"(a) : "l"(p));
    return a;
}
__device__ __forceinline__ void cp16(uint32_t dst, const void* src) {
    asm volatile("cp.async.cg.shared.global [%0], [%1], 16;" :: "r"(dst), "l"(src));
}
#define CP_COMMIT() asm volatile("cp.async.commit_group;")
#define CP_WAIT(n)  asm volatile("cp.async.wait_group %0;" :: "n"(n))

__device__ __forceinline__ void mma_f16(float* c, const uint32_t* a, const uint32_t* b) {
    asm volatile(
        "mma.sync.aligned.m16n8k16.row.col.f32.f16.f16.f32 "
        "{%0,%1,%2,%3}, {%4,%5,%6,%7}, {%8,%9}, {%0,%1,%2,%3};"
        : "+f"(c[0]), "+f"(c[1]), "+f"(c[2]), "+f"(c[3])
        : "r"(a[0]), "r"(a[1]), "r"(a[2]), "r"(a[3]), "r"(b[0]), "r"(b[1]));
}
__device__ __forceinline__ void ldm_x4(uint32_t& r0, uint32_t& r1, uint32_t& r2, uint32_t& r3,
                                       uint32_t addr) {
    asm volatile("ldmatrix.sync.aligned.m8n8.x4.shared.b16 {%0,%1,%2,%3}, [%4];"
                 : "=r"(r0), "=r"(r1), "=r"(r2), "=r"(r3) : "r"(addr));
}
__device__ __forceinline__ void ldm_x4_trans(uint32_t& r0, uint32_t& r1, uint32_t& r2, uint32_t& r3,
                                             uint32_t addr) {
    asm volatile("ldmatrix.sync.aligned.m8n8.x4.trans.shared.b16 {%0,%1,%2,%3}, [%4];"
                 : "=r"(r0), "=r"(r1), "=r"(r2), "=r"(r3) : "r"(addr));
}
__device__ __forceinline__ uint32_t pack2h(__half a, __half b) {
    return ((uint32_t)*(uint16_t*)&b << 16) | *(uint16_t*)&a;
}
__device__ __forceinline__ void split_f16(float v, __half& h, __half& l) {
    h = __float2half_rn(v);
    l = __float2half_rn(v - __half2float(h));
}

// ---------------- kernel 0: fused convx + pack ----------------
#define CONV_BLOCKS ((int)(((size_t)MROWS * IN_DIM / 8) / 256))   // 8192
#define PACK_BLOCKS ((NPROJ * IN_DIM + 255) / 256)                // 1408

__global__ void __launch_bounds__(256) convpack_kernel(
    const float* __restrict__ X,
    const float* __restrict__ Wv, const float* __restrict__ bv,
    const float* __restrict__ Wk, const float* __restrict__ bk,
    const float* __restrict__ Wq, const float* __restrict__ bq,
    const float* __restrict__ Wa, const float* __restrict__ ba) {
    if (blockIdx.x < CONV_BLOCKS) {
        size_t e0 = ((size_t)blockIdx.x * 256 + threadIdx.x) * 8;
        float4 v0 = *(const float4*)&X[e0];
        float4 v1 = *(const float4*)&X[e0 + 4];
        float f[8] = {v0.x, v0.y, v0.z, v0.w, v1.x, v1.y, v1.z, v1.w};
        __align__(16) __half hh[8], ll[8];
#pragma unroll
        for (int i = 0; i < 8; i++) split_f16(f[i], hh[i], ll[i]);
        *(uint4*)&g_Xh[e0] = *(uint4*)hh;
        *(uint4*)&g_Xl[e0] = *(uint4*)ll;
    } else {
        int idx = (blockIdx.x - CONV_BLOCKS) * 256 + threadIdx.x;
        if (idx < NPROJ * IN_DIM) {
            int o = idx >> 9, i = idx & 511;
            float v;
            if (o < 512)       v = Wv[o * IN_DIM + i];
            else if (o < 576)  v = Wk[(o - 512) * IN_DIM + i];
            else if (o < 640)  v = Wq[(o - 576) * IN_DIM + i];
            else               v = Wa[(o - 640) * IN_DIM + i];
            __half h, l; split_f16(v, h, l);
            g_Wh[idx] = h;
            g_Wl[idx] = l;
        }
        if (idx < NPROJ) {
            float v;
            if (idx < 512)      v = bv[idx];
            else if (idx < 576) v = bk[idx - 512];
            else if (idx < 640) v = bq[idx - 576];
            else                v = ba[idx - 640];
            g_bias[idx] = v;
        }
    }
}

// ---------------- kernel 2: projection GEMM, M=128 N=64 tile ----------------------
// v tiles (bx<8): 1-term. k/q tiles (bx=8,9): 2-term. alpha (bx=10): 3-term.
#define GP 72
#define GSTAGE ((2 * 128 + 2 * 64) * GP)
#define GM_SMEM (2 * GSTAGE * 2)

__global__ void __launch_bounds__(256, 2) gemm_mma_kernel() {
    extern __shared__ __half sm_b[];
    uint32_t sb = smem_u32(sm_b);

    int tid = threadIdx.x, wid = tid >> 5, lane = tid & 31;
    int g = lane >> 2, tig = lane & 3;
    int lq = lane & 7, lseg = lane >> 3;
    int wm = wid >> 1;
    int wn = wid & 1;
    int bx = blockIdx.x;
    int m0 = blockIdx.y * 128;
    int n0 = bx * 64;
    bool need2 = (bx >= 8);
    bool need3 = (bx == 10);

    float acc[2][4][4];
#pragma unroll
    for (int i = 0; i < 2; i++)
#pragma unroll
        for (int j = 0; j < 4; j++)
#pragma unroll
            for (int k = 0; k < 4; k++) acc[i][j][k] = 0.f;

#define GCOPY(ch, buf) do {                                                              \
    uint32_t base = sb + (uint32_t)(buf) * (GSTAGE * 2);                                 \
    _Pragma("unroll")                                                                    \
    for (int u = 0; u < 4; u++) {                                                        \
        int l = tid + u * 256;                                                           \
        int rr = l >> 3, qq = l & 7;                                                     \
        size_t gx = (size_t)(m0 + rr) * IN_DIM + (ch) * 64 + qq * 8;                     \
        uint32_t so = (uint32_t)(rr * GP + qq * 8) * 2;                                  \
        cp16(base + so, &g_Xh[gx]);                                                      \
        if (need3) cp16(base + 128 * GP * 2 + so, &g_Xl[gx]);                            \
    }                                                                                    \
    _Pragma("unroll")                                                                    \
    for (int u = 0; u < 2; u++) {                                                        \
        int l = tid + u * 256;                                                           \
        int rr = l >> 3, qq = l & 7;                                                     \
        size_t gw = (size_t)(n0 + rr) * IN_DIM + (ch) * 64 + qq * 8;                     \
        uint32_t so = (uint32_t)(rr * GP + qq * 8) * 2;                                  \
        cp16(base + 2 * 128 * GP * 2 + so, &g_Wh[gw]);                                   \
        if (need2) cp16(base + (2 * 128 + 64) * GP * 2 + so, &g_Wl[gw]);                 \
    }                                                                                    \
} while (0)

    GCOPY(0, 0);
    CP_COMMIT();

    int arow = (lseg & 1) * 8 + lq;
    int asel = (lseg >> 1) * 8;
    int brow = (lseg >> 1) * 8 + lq;
    int bsel = (lseg & 1) * 8;

    for (int ch = 0; ch < 8; ch++) {
        if (ch + 1 < 8) { GCOPY(ch + 1, (ch + 1) & 1); CP_COMMIT(); }
        if (ch + 1 < 8) CP_WAIT(1); else CP_WAIT(0);
        __syncthreads();

        uint32_t uXh = sb + (uint32_t)(ch & 1) * (GSTAGE * 2);
        uint32_t uXl = uXh + 128 * GP * 2;
        uint32_t uWh = uXl + 128 * GP * 2;
        uint32_t uWl = uWh + 64 * GP * 2;

#pragma unroll
        for (int ks = 0; ks < 64; ks += 16) {
            uint32_t Ah[2][4], Al[2][4], Bh[4][2], Bl[4][2];
#pragma unroll
            for (int mi = 0; mi < 2; mi++) {
                uint32_t off = (uint32_t)((wm * 32 + mi * 16 + arow) * GP + ks + asel) * 2;
                ldm_x4(Ah[mi][0], Ah[mi][1], Ah[mi][2], Ah[mi][3], uXh + off);
                if (need3) ldm_x4(Al[mi][0], Al[mi][1], Al[mi][2], Al[mi][3], uXl + off);
            }
#pragma unroll
            for (int njp = 0; njp < 2; njp++) {
                uint32_t off = (uint32_t)((wn * 32 + njp * 16 + brow) * GP + ks + bsel) * 2;
                ldm_x4(Bh[njp * 2][0], Bh[njp * 2][1], Bh[njp * 2 + 1][0], Bh[njp * 2 + 1][1], uWh + off);
                if (need2) ldm_x4(Bl[njp * 2][0], Bl[njp * 2][1], Bl[njp * 2 + 1][0], Bl[njp * 2 + 1][1], uWl + off);
            }
#pragma unroll
            for (int mi = 0; mi < 2; mi++)
#pragma unroll
                for (int nj = 0; nj < 4; nj++) {
                    mma_f16(acc[mi][nj], Ah[mi], Bh[nj]);
                    if (need2) mma_f16(acc[mi][nj], Ah[mi], Bl[nj]);
                    if (need3) mma_f16(acc[mi][nj], Al[mi], Bh[nj]);
                }
        }
        __syncthreads();
    }

    bool alpha_tile = (bx == 10);
    bool v_tile = (bx < 8);
#pragma unroll
    for (int mi = 0; mi < 2; mi++) {
        int r0 = m0 + wm * 32 + mi * 16 + g;
#pragma unroll
        for (int nj = 0; nj < 4; nj++) {
            int col = n0 + wn * 32 + nj * 8 + tig * 2;
            float b0 = g_bias[col], b1 = g_bias[col + 1];
            float v0 = acc[mi][nj][0] + b0, v1 = acc[mi][nj][1] + b1;
            float v2 = acc[mi][nj][2] + b0, v3 = acc[mi][nj][3] + b1;
            if (v_tile) {
                *(uint32_t*)&g_Vh[(size_t)r0 * D_V + col] =
                    pack2h(__float2half_rn(v0), __float2half_rn(v1));
                *(uint32_t*)&g_Vh[(size_t)(r0 + 8) * D_V + col] =
                    pack2h(__float2half_rn(v2), __float2half_rn(v3));
            } else {
                if (alpha_tile) {
                    v0 = 1.f / (1.f + expf(-v0));
                    v1 = 1.f / (1.f + expf(-v1));
                    v2 = 1.f / (1.f + expf(-v2));
                    v3 = 1.f / (1.f + expf(-v3));
                }
                float2 lo; lo.x = v0; lo.y = v1;
                float2 hi; hi.x = v2; hi.y = v3;
                *(float2*)&g_proj[(size_t)r0 * NPROJ + col] = lo;
                *(float2*)&g_proj[(size_t)(r0 + 8) * NPROJ + col] = hi;
            }
        }
    }
#undef GCOPY
}

// ---------------- kernel 3: per-chunk prep (512 threads) -------------------------
#define PREP_SMEM (3 * 128 * 65 * 4)
__global__ void __launch_bounds__(512, 2) prep_kernel() {
    extern __shared__ float sm[];
    float* sp  = sm;
    float* sqt = sm + 128 * 65;
    float* skt = sm + 2 * 128 * 65;

    int b = blockIdx.x, c = blockIdx.y;
    int tid = threadIdx.x;
    size_t aqbase = (size_t)(c * BATCH + b) * CHUNK * AQW;
    size_t kbase  = (size_t)(c * BATCH + b) * CHUNK * D_K;

#pragma unroll
    for (int j = 0; j < 4; j++) {
        int l  = tid + j * 512;
        int t  = l >> 4;
        int c4 = (l & 15) * 4;
        const float* rowp = g_proj + (size_t)((c * CHUNK + t) * BATCH + b) * NPROJ;
        float4 av = *(const float4*)&rowp[640 + c4];
        skt[t * 65 + c4 + 0] = av.x; skt[t * 65 + c4 + 1] = av.y;
        skt[t * 65 + c4 + 2] = av.z; skt[t * 65 + c4 + 3] = av.w;
    }
    __syncthreads();

    if (tid < D_K) {
        float p = 1.f;
        for (int t = 0; t < CHUNK; t++) {
            p *= fmaxf(skt[t * 65 + tid], EPS_F);
            sp[t * 65 + tid] = p;
        }
        g_pend[(c * BATCH + b) * D_K + tid] = p;
    }
    __syncthreads();

#pragma unroll
    for (int j = 0; j < 4; j++) {
        int l  = tid + j * 512;
        int t  = l >> 4;
        int c4 = (l & 15) * 4;
        const float* rowp = g_proj + (size_t)((c * CHUNK + t) * BATCH + b) * NPROJ;
        float4 qv = *(const float4*)&rowp[576 + c4];
        float4 kv = *(const float4*)&rowp[512 + c4];
        float p0 = sp[t * 65 + c4 + 0], p1 = sp[t * 65 + c4 + 1];
        float p2 = sp[t * 65 + c4 + 2], p3 = sp[t * 65 + c4 + 3];
        float pe0 = sp[127 * 65 + c4 + 0], pe1 = sp[127 * 65 + c4 + 1];
        float pe2 = sp[127 * 65 + c4 + 2], pe3 = sp[127 * 65 + c4 + 3];
        float q0 = qv.x * p0, q1 = qv.y * p1, q2 = qv.z * p2, q3 = qv.w * p3;
        float k0 = kv.x / (p0 + EPS_F), k1 = kv.y / (p1 + EPS_F);
        float k2 = kv.z / (p2 + EPS_F), k3 = kv.w / (p3 + EPS_F);
        sqt[t * 65 + c4 + 0] = q0; sqt[t * 65 + c4 + 1] = q1;
        sqt[t * 65 + c4 + 2] = q2; sqt[t * 65 + c4 + 3] = q3;
        skt[t * 65 + c4 + 0] = k0; skt[t * 65 + c4 + 1] = k1;
        skt[t * 65 + c4 + 2] = k2; skt[t * 65 + c4 + 3] = k3;
        __half h0 = __float2half_rn(q0), h1 = __float2half_rn(q1);
        __half h2 = __float2half_rn(q2), h3 = __float2half_rn(q3);
        uint32_t* ph = (uint32_t*)&g_AQh[aqbase + t * AQW + 128 + c4];
        ph[0] = pack2h(h0, h1); ph[1] = pack2h(h2, h3);
        __half e0 = __float2half_rn(k0 * pe0), e1 = __float2half_rn(k1 * pe1);
        __half e2 = __float2half_rn(k2 * pe2), e3 = __float2half_rn(k3 * pe3);
        uint32_t* kh = (uint32_t*)&g_kpeh[kbase + t * D_K + c4];
        kh[0] = pack2h(e0, e1); kh[1] = pack2h(e2, e3);
    }
    __syncthreads();

    // A[t][s]: 512 threads -> 32 t-groups x 16 s-lanes; each 4 t x 8 s
    int sxl = tid & 15;
    int t0  = (tid >> 4) * 4;
    float acc[4][8];
#pragma unroll
    for (int i = 0; i < 4; i++)
#pragma unroll
        for (int j = 0; j < 8; j++) acc[i][j] = 0.f;

    for (int n = 0; n < D_K; n++) {
        float qv[4], kv[8];
#pragma unroll
        for (int i = 0; i < 4; i++) qv[i] = sqt[(t0 + i) * 65 + n];
#pragma unroll
        for (int j = 0; j < 8; j++) kv[j] = skt[(sxl + 16 * j) * 65 + n];
#pragma unroll
        for (int i = 0; i < 4; i++)
#pragma unroll
            for (int j = 0; j < 8; j++)
                acc[i][j] = fmaf(qv[i], kv[j], acc[i][j]);
    }
#pragma unroll
    for (int i = 0; i < 4; i++) {
        int t = t0 + i;
#pragma unroll
        for (int j = 0; j < 8; j++) {
            int s = sxl + 16 * j;
            float val = (t >= s) ? acc[i][j] : 0.f;
            g_AQh[aqbase + t * AQW + s] = __float2half_rn(val);
        }
    }
}

// ---------------- kernel 4: contrib via HMMA 1-term ----------------
#define CPP 72
#define CM_SMEM (2 * 128 * CPP * 2)

__global__ void __launch_bounds__(256) contrib_kernel() {
    extern __shared__ __half csm[];
    uint32_t uKh = smem_u32(csm);
    uint32_t uVh = uKh + 128 * CPP * 2;

    int d0 = blockIdx.x * 64, c = blockIdx.y, b = blockIdx.z;
    int tid = threadIdx.x, wid = tid >> 5, lane = tid & 31;
    int g = lane >> 2, tig = lane & 3;
    int lq = lane & 7, lseg = lane >> 3;
    int wn = wid & 1;
    int wd = wid >> 1;

    size_t kbase = (size_t)(c * BATCH + b) * CHUNK * D_K;

#pragma unroll
    for (int u = 0; u < 2; u++) {
        int l = tid + u * 256;
        int rr = l >> 3, qq = l & 7;
        uint32_t so = (uint32_t)(rr * CPP + qq * 8) * 2;
        cp16(uKh + so, &g_kpeh[kbase + rr * D_K + qq * 8]);
        size_t vs = (size_t)((c * CHUNK + rr) * BATCH + b) * D_V + d0 + qq * 8;
        cp16(uVh + so, &g_Vh[vs]);
    }
    CP_COMMIT();
#pragma unroll
    for (int u = 2; u < 4; u++) {
        int l = tid + u * 256;
        int rr = l >> 3, qq = l & 7;
        uint32_t so = (uint32_t)(rr * CPP + qq * 8) * 2;
        cp16(uKh + so, &g_kpeh[kbase + rr * D_K + qq * 8]);
        size_t vs = (size_t)((c * CHUNK + rr) * BATCH + b) * D_V + d0 + qq * 8;
        cp16(uVh + so, &g_Vh[vs]);
    }
    CP_COMMIT();

    float acc[2][2][4];
#pragma unroll
    for (int i = 0; i < 2; i++)
#pragma unroll
        for (int j = 0; j < 2; j++)
#pragma unroll
            for (int k = 0; k < 4; k++) acc[i][j][k] = 0.f;

#pragma unroll
    for (int half = 0; half < 2; half++) {
        if (half == 0) CP_WAIT(1); else CP_WAIT(0);
        __syncthreads();
#pragma unroll
        for (int kk = 0; kk < 64; kk += 16) {
            int ks = half * 64 + kk;
            uint32_t Ah[2][4], Bh[2][2];
            uint32_t arow = ks + (lseg >> 1) * 8 + lq;
#pragma unroll
            for (int mi = 0; mi < 2; mi++) {
                uint32_t col = wn * 32 + mi * 16 + (lseg & 1) * 8;
                uint32_t off = (arow * CPP + col) * 2;
                ldm_x4_trans(Ah[mi][0], Ah[mi][1], Ah[mi][2], Ah[mi][3], uKh + off);
            }
            {
                uint32_t brow = ks + (lseg & 1) * 8 + lq;
                uint32_t col = wd * 16 + (lseg >> 1) * 8;
                uint32_t off = (brow * CPP + col) * 2;
                ldm_x4_trans(Bh[0][0], Bh[0][1], Bh[1][0], Bh[1][1], uVh + off);
            }
#pragma unroll
            for (int mi = 0; mi < 2; mi++)
#pragma unroll
                for (int nj = 0; nj < 2; nj++)
                    mma_f16(acc[mi][nj], Ah[mi], Bh[nj]);
        }
    }

    float* Wb = g_Wc + (size_t)(c * BATCH + b) * D_K * D_V;
#pragma unroll
    for (int mi = 0; mi < 2; mi++) {
        int n = wn * 32 + mi * 16 + g;
#pragma unroll
        for (int nj = 0; nj < 2; nj++) {
            int d = d0 + wd * 16 + nj * 8 + tig * 2;
            float2 lo; lo.x = acc[mi][nj][0]; lo.y = acc[mi][nj][1];
            float2 hi; hi.x = acc[mi][nj][2]; hi.y = acc[mi][nj][3];
            *(float2*)&Wb[(size_t)n * D_V + d] = lo;
            *(float2*)&Wb[(size_t)(n + 8) * D_V + d] = hi;
        }
    }
}

// ---------------- kernel 5: elementwise state scan; emit S_start fp16 -------------
__global__ void __launch_bounds__(256) state_scan_kernel() {
    int g = blockIdx.x * 256 + threadIdx.x;
    int bn = g >> 9;
    float s = 0.f;
    for (int c = 0; c < NC; c++) {
        size_t idx = (size_t)c * SEG + g;
        g_Sh[idx] = __float2half_rn(s);
        s = fmaf(s, g_pend[c * (BATCH * D_K) + bn], g_Wc[idx]);
    }
}

// ---------------- kernel 6: Y = [A|q_t] @ [V;S], d-tile 128, causal-zero skip -----
#define YPA 72
#define YPB 136
#define YSTAGE (128 * YPA + 64 * YPB)
#define YG_SMEM (2 * YSTAGE * 2)

__global__ void __launch_bounds__(128, 2) ygemm_mma_kernel(float* __restrict__ out) {
    extern __shared__ __half ysm[];
    uint32_t sb = smem_u32(ysm);

    int d0 = blockIdx.x * 128;
    int c = blockIdx.y, b = blockIdx.z;
    int tid = threadIdx.x, w = tid >> 5, lane = tid & 31;
    int g = lane >> 2, tig = lane & 3;
    int lq = lane & 7, lseg = lane >> 3;
    int arow = (lseg & 1) * 8 + lq;
    int asel = (lseg >> 1) * 8;

    size_t aqbase = (size_t)(c * BATCH + b) * CHUNK * AQW;
    size_t sbase  = (size_t)(c * BATCH + b) * D_K * D_V;

    float acc[2][16][4];
#pragma unroll
    for (int i = 0; i < 2; i++)
#pragma unroll
        for (int j = 0; j < 16; j++)
#pragma unroll
            for (int k = 0; k < 4; k++) acc[i][j][k] = 0.f;

#define YCOPY(ch, buf) do {                                                              \
    uint32_t base = sb + (uint32_t)(buf) * (YSTAGE * 2);                                 \
    _Pragma("unroll")                                                                    \
    for (int u = 0; u < 8; u++) {                                                        \
        int l = tid + u * 128;                                                           \
        int rr = l >> 3, qq = l & 7;                                                     \
        size_t src = aqbase + rr * AQW + (ch) * 64 + qq * 8;                             \
        uint32_t so = (uint32_t)(rr * YPA + qq * 8) * 2;                                 \
        cp16(base + so, &g_AQh[src]);                                                    \
    }                                                                                    \
    _Pragma("unroll")                                                                    \
    for (int u = 0; u < 8; u++) {                                                        \
        int l = tid + u * 128;                                                           \
        int rr = l >> 4, qq = l & 15;                                                    \
        uint32_t so = (uint32_t)(128 * YPA + rr * YPB + qq * 8) * 2;                     \
        if ((ch) < 2) {                                                                  \
            size_t src = (size_t)((c * CHUNK + (ch) * 64 + rr) * BATCH + b) * D_V + d0 + qq * 8; \
            cp16(base + so, &g_Vh[src]);                                                 \
        } else {                                                                         \
            size_t src = sbase + (size_t)rr * D_V + d0 + qq * 8;                         \
            cp16(base + so, &g_Sh[src]);                                                 \
        }                                                                                \
    }                                                                                    \
} while (0)

    YCOPY(0, 0);
    CP_COMMIT();

    for (int ch = 0; ch < 3; ch++) {
        if (ch + 1 < 3) { YCOPY(ch + 1, (ch + 1) & 1); CP_COMMIT(); }
        if (ch + 1 < 3) CP_WAIT(1); else CP_WAIT(0);
        __syncthreads();

        bool active = !(ch == 1 && w < 2) && !(ch == 2 && c == 0);
        if (active) {
            uint32_t uA = sb + (uint32_t)(ch & 1) * (YSTAGE * 2);
            uint32_t uB = uA + 128 * YPA * 2;

#pragma unroll
            for (int ks = 0; ks < 64; ks += 16) {
                uint32_t Ah[2][4], Bh[16][2];
#pragma unroll
                for (int mi = 0; mi < 2; mi++) {
                    uint32_t off = (uint32_t)((w * 32 + mi * 16 + arow) * YPA + ks + asel) * 2;
                    ldm_x4(Ah[mi][0], Ah[mi][1], Ah[mi][2], Ah[mi][3], uA + off);
                }
                uint32_t row = ks + (lseg & 1) * 8 + lq;
#pragma unroll
                for (int nbs = 0; nbs < 8; nbs++) {
                    uint32_t col = nbs * 16 + (lseg >> 1) * 8;
                    uint32_t off = (row * YPB + col) * 2;
                    ldm_x4_trans(Bh[nbs * 2][0], Bh[nbs * 2][1], Bh[nbs * 2 + 1][0], Bh[nbs * 2 + 1][1], uB + off);
                }
#pragma unroll
                for (int mi = 0; mi < 2; mi++)
#pragma unroll
                    for (int nj = 0; nj < 16; nj++)
                        mma_f16(acc[mi][nj], Ah[mi], Bh[nj]);
            }
        }
        __syncthreads();
    }
#undef YCOPY

#pragma unroll
    for (int mi = 0; mi < 2; mi++) {
        int t = w * 32 + mi * 16 + g;
#pragma unroll
        for (int nj = 0; nj < 16; nj++) {
            int col = d0 + nj * 8 + tig * 2;
            float2 lo; lo.x = acc[mi][nj][0]; lo.y = acc[mi][nj][1];
            float2 hi; hi.x = acc[mi][nj][2]; hi.y = acc[mi][nj][3];
            *(float2*)&out[(size_t)((c * CHUNK + t) * BATCH + b) * D_V + col] = lo;
            *(float2*)&out[(size_t)((c * CHUNK + t + 8) * BATCH + b) * D_V + col] = hi;
        }
    }
}

// ---------------- launch ----------------
extern "C" void kernel_launch(void* const* d_in, const int* in_sizes, int n_in,
                              void* d_out, int out_size) {
    const float* x  = (const float*)d_in[0];
    const float* Wv = (const float*)d_in[1];
    const float* bv = (const float*)d_in[2];
    const float* Wk = (const float*)d_in[3];
    const float* bk = (const float*)d_in[4];
    const float* Wq = (const float*)d_in[5];
    const float* bq = (const float*)d_in[6];
    const float* Wa = (const float*)d_in[7];
    const float* ba = (const float*)d_in[8];
    float* out = (float*)d_out;

    cudaFuncSetAttribute(prep_kernel, cudaFuncAttributeMaxDynamicSharedMemorySize, PREP_SMEM);
    cudaFuncSetAttribute(gemm_mma_kernel, cudaFuncAttributeMaxDynamicSharedMemorySize, GM_SMEM);
    cudaFuncSetAttribute(contrib_kernel, cudaFuncAttributeMaxDynamicSharedMemorySize, CM_SMEM);
    cudaFuncSetAttribute(ygemm_mma_kernel, cudaFuncAttributeMaxDynamicSharedMemorySize, YG_SMEM);

    convpack_kernel<<<CONV_BLOCKS + PACK_BLOCKS, 256>>>(x, Wv, bv, Wk, bk, Wq, bq, Wa, ba);
    gemm_mma_kernel<<<dim3(11, MROWS / 128), 256, GM_SMEM>>>();
    prep_kernel<<<dim3(BATCH, NC), 512, PREP_SMEM>>>();
    contrib_kernel<<<dim3(D_V / 64, NC, BATCH), 256, CM_SMEM>>>();
    state_scan_kernel<<<SEG / 256, 256>>>();
    ygemm_mma_kernel<<<dim3(D_V / 128, NC, BATCH), 128, YG_SMEM>>>(out);
}